// round 1
// baseline (speedup 1.0000x reference)
#include <cuda_runtime.h>
#include <cstdint>

// Problem constants
#define N_B   4096
#define N_T   256
#define HID   128
#define TILE_M 64

// Shared layout (floats)
#define S_W2 (128*128)   // 16384
#define S_H  (64*128)    //  8192
#define S_W1 (8*128)     //  1024
#define S_F  (64*8)      //   512
#define SMEM_FLOATS (S_W2 + S_H + S_W1 + S_F + 128 + 128 + 256 + 2)
#define SMEM_BYTES  (SMEM_FLOATS * 4)

// ---------- f32x2 packed helpers (FFMA2 is PTX-only on sm_103a) ----------
__device__ __forceinline__ unsigned long long pack_dup(float v) {
    unsigned long long r;
    asm("mov.b64 %0, {%1, %1};" : "=l"(r) : "f"(v));
    return r;
}
__device__ __forceinline__ unsigned long long pack2f(float a, float b) {
    unsigned long long r;
    asm("mov.b64 %0, {%1, %2};" : "=l"(r) : "f"(a), "f"(b));
    return r;
}
__device__ __forceinline__ unsigned long long ffma2(unsigned long long a,
                                                    unsigned long long b,
                                                    unsigned long long c) {
    unsigned long long d;
    asm("fma.rn.f32x2 %0, %1, %2, %3;" : "=l"(d) : "l"(a), "l"(b), "l"(c));
    return d;
}
__device__ __forceinline__ float2 unpack2(unsigned long long v) {
    float2 r;
    asm("mov.b64 {%0, %1}, %2;" : "=f"(r.x), "=f"(r.y) : "l"(v));
    return r;
}

// DIR: 0 = fwd MLP (writes score[b, i+1], zeros score[b,0])
//      1 = bwd MLP (adds to score[b, i])
//      2 = init MLP (adds to score[b, 0]); rows indexed by batch
template <int DIR>
__global__ __launch_bounds__(256, 2)
void mlp_kernel(const float* __restrict__ x, const float* __restrict__ t,
                const float* __restrict__ W1, const float* __restrict__ b1v,
                const float* __restrict__ W2, const float* __restrict__ b2v,
                const float* __restrict__ W3, const float* __restrict__ b3v,
                float* __restrict__ out, int ntiles)
{
    extern __shared__ float sm[];
    float* sW2 = sm;
    float* sH  = sW2 + S_W2;
    float* sW1 = sH  + S_H;
    float* sF  = sW1 + S_W1;
    float* sB1 = sF  + S_F;
    float* sB2 = sB1 + 128;
    float* sW3 = sB2 + 128;
    float* sB3 = sW3 + 256;

    const int tid = threadIdx.x;
    const int w = tid >> 5;   // warp id: rows w*8 .. w*8+7
    const int l = tid & 31;   // lane: cols l*4 .. l*4+3
    constexpr int KIN = (DIR == 2) ? 3 : 8;

    // ---- load weights once (persistent block) ----
    {
        const float4* W2v = (const float4*)W2;
        float4* dW2 = (float4*)sW2;
        for (int idx = tid; idx < S_W2 / 4; idx += 256) dW2[idx] = W2v[idx];
        for (int idx = tid; idx < KIN * 128; idx += 256) sW1[idx] = W1[idx];
        if (tid < 128) { sB1[tid] = b1v[tid]; sB2[tid] = b2v[tid]; }
        if (tid < 256) sW3[tid] = W3[tid];   // (128,2) row-major
        if (tid < 2)   sB3[tid] = b3v[tid];
    }
    // first __syncthreads below covers weight visibility

    for (int tt = blockIdx.x; tt < ntiles; tt += gridDim.x) {
        int b, i0;
        if (DIR == 2) { b = 0; i0 = tt * TILE_M; }        // row = batch index
        else          { b = tt >> 2; i0 = (tt & 3) * TILE_M; }

        // ---- build features for 64 rows ----
        if (tid < TILE_M) {
            const int m = tid;
            if (DIR == 2) {
                const int br = i0 + m;
                const float2 x0 = *(const float2*)(x + (size_t)br * 257 * 2);
                const float tb = t[br];
                float* f = sF + m * 8;
                f[0] = x0.x; f[1] = x0.y; f[2] = tb;
                f[3] = 0.f; f[4] = 0.f; f[5] = 0.f; f[6] = 0.f; f[7] = 0.f;
            } else {
                const int i = i0 + m;                 // valid if i < 255
                const float* xb = x + (size_t)b * 257 * 2;
                const float2 xi  = *(const float2*)(xb + i * 2);
                const float2 xi1 = *(const float2*)(xb + (i + 1) * 2);  // i+1<=256 always in-bounds
                const float2 pt  = *(const float2*)(xb + 256 * 2);
                const float tb = t[b];
                float* f = sF + m * 8;
                if (DIR == 0) {
                    f[0] = xi1.x; f[1] = xi1.y; f[2] = tb;
                    f[3] = xi.x;  f[4] = xi.y;  f[5] = (float)(i + 1) * (1.f / 256.f);
                    f[6] = pt.x;  f[7] = pt.y;
                } else {
                    f[0] = xi.x;  f[1] = xi.y;  f[2] = tb;
                    f[3] = xi1.x; f[4] = xi1.y; f[5] = (float)i * (1.f / 256.f);
                    f[6] = pt.x;  f[7] = pt.y;
                }
            }
        }
        if (DIR == 0) {
            // score[b, 0] = 0 (output buffer is poisoned; bwd/init accumulate later)
            if ((tt & 3) == 0 && tid == 64)
                *(float2*)(out + (size_t)b * N_T * 2) = make_float2(0.f, 0.f);
        }
        __syncthreads();

        // ---- L1: H = relu(F @ W1 + b1), each thread: 8 rows x 4 cols ----
        {
            float4 w1v[KIN];
            #pragma unroll
            for (int k = 0; k < KIN; k++) w1v[k] = *(const float4*)(sW1 + k * 128 + l * 4);
            const float4 b1q = *(const float4*)(sB1 + l * 4);
            #pragma unroll
            for (int j = 0; j < 8; j++) {
                const int m = w * 8 + j;
                float a0 = b1q.x, a1 = b1q.y, a2 = b1q.z, a3 = b1q.w;
                #pragma unroll
                for (int k = 0; k < KIN; k++) {
                    const float f = sF[m * 8 + k];
                    a0 += f * w1v[k].x; a1 += f * w1v[k].y;
                    a2 += f * w1v[k].z; a3 += f * w1v[k].w;
                }
                float4 hv;
                hv.x = fmaxf(a0, 0.f); hv.y = fmaxf(a1, 0.f);
                hv.z = fmaxf(a2, 0.f); hv.w = fmaxf(a3, 0.f);
                *(float4*)(sH + m * 128 + l * 4) = hv;
            }
        }
        __syncthreads();

        // ---- L2: ACC = H @ W2 + b2, f32x2 packed (2 cols per 64-bit acc) ----
        unsigned long long acc[8][2];
        {
            const float4 b2q = *(const float4*)(sB2 + l * 4);
            const unsigned long long bi0 = pack2f(b2q.x, b2q.y);
            const unsigned long long bi1 = pack2f(b2q.z, b2q.w);
            #pragma unroll
            for (int j = 0; j < 8; j++) { acc[j][0] = bi0; acc[j][1] = bi1; }

            const float* hbase = sH + (size_t)w * 8 * 128;
            #pragma unroll 2
            for (int k = 0; k < 128; k += 4) {
                const ulonglong2 q0 = *(const ulonglong2*)(sW2 + (k + 0) * 128 + l * 4);
                const ulonglong2 q1 = *(const ulonglong2*)(sW2 + (k + 1) * 128 + l * 4);
                const ulonglong2 q2 = *(const ulonglong2*)(sW2 + (k + 2) * 128 + l * 4);
                const ulonglong2 q3 = *(const ulonglong2*)(sW2 + (k + 3) * 128 + l * 4);
                #pragma unroll
                for (int j = 0; j < 8; j++) {
                    const float4 av = *(const float4*)(hbase + j * 128 + k);
                    unsigned long long a;
                    a = pack_dup(av.x);
                    acc[j][0] = ffma2(a, q0.x, acc[j][0]);
                    acc[j][1] = ffma2(a, q0.y, acc[j][1]);
                    a = pack_dup(av.y);
                    acc[j][0] = ffma2(a, q1.x, acc[j][0]);
                    acc[j][1] = ffma2(a, q1.y, acc[j][1]);
                    a = pack_dup(av.z);
                    acc[j][0] = ffma2(a, q2.x, acc[j][0]);
                    acc[j][1] = ffma2(a, q2.y, acc[j][1]);
                    a = pack_dup(av.w);
                    acc[j][0] = ffma2(a, q3.x, acc[j][0]);
                    acc[j][1] = ffma2(a, q3.y, acc[j][1]);
                }
            }
        }

        // ---- L3: out = relu(ACC) @ W3 + b3, warp-reduce over 128 cols ----
        {
            const float4 w3a = *(const float4*)(sW3 + l * 8);      // cols n0,n0+1 (o=0,1 each)
            const float4 w3b = *(const float4*)(sW3 + l * 8 + 4);  // cols n0+2,n0+3
            const float b30 = sB3[0], b31 = sB3[1];
            #pragma unroll
            for (int j = 0; j < 8; j++) {
                const float2 v01 = unpack2(acc[j][0]);
                const float2 v23 = unpack2(acc[j][1]);
                const float r0 = fmaxf(v01.x, 0.f), r1 = fmaxf(v01.y, 0.f);
                const float r2 = fmaxf(v23.x, 0.f), r3 = fmaxf(v23.y, 0.f);
                float p0 = r0 * w3a.x + r1 * w3a.z + r2 * w3b.x + r3 * w3b.z;
                float p1 = r0 * w3a.y + r1 * w3a.w + r2 * w3b.y + r3 * w3b.w;
                #pragma unroll
                for (int s = 16; s >= 1; s >>= 1) {
                    p0 += __shfl_xor_sync(0xffffffffu, p0, s);
                    p1 += __shfl_xor_sync(0xffffffffu, p1, s);
                }
                if (l == j) {
                    p0 += b30; p1 += b31;
                    const int m = w * 8 + j;
                    if (DIR == 2) {
                        const int br = i0 + m;
                        float2* o = (float2*)(out + (size_t)br * N_T * 2);
                        const float2 old = *o;
                        *o = make_float2(old.x + p0, old.y + p1);
                    } else {
                        const int i = i0 + m;
                        if (i < N_T - 1) {
                            if (DIR == 0) {
                                *(float2*)(out + ((size_t)b * N_T + i + 1) * 2) =
                                    make_float2(p0, p1);
                            } else {
                                float2* o = (float2*)(out + ((size_t)b * N_T + i) * 2);
                                const float2 old = *o;
                                *o = make_float2(old.x + p0, old.y + p1);
                            }
                        }
                    }
                }
            }
        }
        // No trailing barrier needed: next iteration's sF write only races L2/L3
        // (which never read sF), and the next __syncthreads precedes sH overwrite.
    }
}

extern "C" void kernel_launch(void* const* d_in, const int* in_sizes, int n_in,
                              void* d_out, int out_size)
{
    (void)in_sizes; (void)n_in; (void)out_size;
    const float* x  = (const float*)d_in[0];
    const float* t  = (const float*)d_in[1];
    const float* fw_W1 = (const float*)d_in[2];
    const float* fw_b1 = (const float*)d_in[3];
    const float* fw_W2 = (const float*)d_in[4];
    const float* fw_b2 = (const float*)d_in[5];
    const float* fw_W3 = (const float*)d_in[6];
    const float* fw_b3 = (const float*)d_in[7];
    const float* bw_W1 = (const float*)d_in[8];
    const float* bw_b1 = (const float*)d_in[9];
    const float* bw_W2 = (const float*)d_in[10];
    const float* bw_b2 = (const float*)d_in[11];
    const float* bw_W3 = (const float*)d_in[12];
    const float* bw_b3 = (const float*)d_in[13];
    const float* in_W1 = (const float*)d_in[14];
    const float* in_b1 = (const float*)d_in[15];
    const float* in_W2 = (const float*)d_in[16];
    const float* in_b2 = (const float*)d_in[17];
    const float* in_W3 = (const float*)d_in[18];
    const float* in_b3 = (const float*)d_in[19];
    float* out = (float*)d_out;

    cudaFuncSetAttribute(mlp_kernel<0>, cudaFuncAttributeMaxDynamicSharedMemorySize, SMEM_BYTES);
    cudaFuncSetAttribute(mlp_kernel<1>, cudaFuncAttributeMaxDynamicSharedMemorySize, SMEM_BYTES);
    cudaFuncSetAttribute(mlp_kernel<2>, cudaFuncAttributeMaxDynamicSharedMemorySize, SMEM_BYTES);

    const int ntiles_dir = (N_B) * 4;           // 4 tiles of 64 rows per batch (255 rows)
    const int nblk = 304;                       // ~2 blocks/SM, persistent

    // Order matters: fwd writes (and zeros pos 0), bwd accumulates, init accumulates.
    mlp_kernel<0><<<nblk, 256, SMEM_BYTES>>>(x, t, fw_W1, fw_b1, fw_W2, fw_b2,
                                             fw_W3, fw_b3, out, ntiles_dir);
    mlp_kernel<1><<<nblk, 256, SMEM_BYTES>>>(x, t, bw_W1, bw_b1, bw_W2, bw_b2,
                                             bw_W3, bw_b3, out, ntiles_dir);
    mlp_kernel<2><<<N_B / TILE_M, 256, SMEM_BYTES>>>(x, t, in_W1, in_b1, in_W2, in_b2,
                                                     in_W3, in_b3, out, N_B / TILE_M);
}